// round 1
// baseline (speedup 1.0000x reference)
#include <cuda_runtime.h>
#include <math.h>
#include <float.h>

#define NTR   20000
#define NTE   10000
#define NB    1024
#define NBINS 15
#define NMC   10000
#define NPTS  (NBINS * NMC)   // 150000
#define NCLS  10
#define CHUNK 2048
#define NCHUNKS 16
#define TILE  256
#define KDE_GRID 2048

// c = log2(e) / (2*BW^2) = 1.4426950408889634 / 0.18
#define CC   8.014972449383130f
#define CC2  16.029944898766260f
// KDE_NORM = 2*pi*BW*BW
#define KDE_NORM_D 0.5654866776461628

// ---------- device scratch (static: no allocations allowed) ----------
__device__ float4 g_train[NTR];
__device__ float4 g_test[NTE];
__device__ float4 g_batch[NB];
__device__ float  g_px[NPTS], g_py[NPTS], g_pe[NPTS];
__device__ int    g_pbin[NPTS];
__device__ float  g_sums0[NPTS], g_sums1[NPTS], g_sums2[NPTS];
__device__ int    g_M, g_cnt;
__device__ int    g_htr[NBINS], g_hte[NBINS];
__device__ double g_integral[NBINS];

// chunk table: arrays 0=train(10 chunks),1=test(5 chunks),2=batch(1 chunk)
__constant__ int c_carr[NCHUNKS]   = {0,0,0,0,0,0,0,0,0,0, 1,1,1,1,1, 2};
__constant__ int c_cstart[NCHUNKS] = {0,2048,4096,6144,8192,10240,12288,14336,16384,18432,
                                      0,2048,4096,6144,8192, 0};
__constant__ int c_clen[NCHUNKS]   = {2048,2048,2048,2048,2048,2048,2048,2048,2048,1568,
                                      2048,2048,2048,2048,1808, 1024};

__device__ __forceinline__ float ex2f(float x) {
    float y;
    asm("ex2.approx.ftz.f32 %0, %1;" : "=f"(y) : "f"(x));
    return y;
}

// ---------- kernels ----------
__global__ void k_zero() {
    int i = blockIdx.x * blockDim.x + threadIdx.x;
    if (i < NPTS) { g_sums0[i] = 0.f; g_sums1[i] = 0.f; g_sums2[i] = 0.f; }
    if (i == 0) { g_M = 0; g_cnt = 0; }
    if (i < NBINS) { g_htr[i] = 0; g_hte[i] = 0; g_integral[i] = 0.0; }
}

__global__ void k_prep(const float* __restrict__ trx, const float* __restrict__ tex,
                       const float* __restrict__ bx, const int* __restrict__ by,
                       const int* __restrict__ bp) {
    int i = blockIdx.x * blockDim.x + threadIdx.x;
    if (i < NTR) {
        float x = trx[2*i], y = trx[2*i+1];
        g_train[i] = make_float4(CC2*x, CC2*y, -CC*(x*x + y*y), 0.f);
    }
    if (i < NTE) {
        float x = tex[2*i], y = tex[2*i+1];
        g_test[i] = make_float4(CC2*x, CC2*y, -CC*(x*x + y*y), 0.f);
    }
    if (i < NB) {
        float x = bx[2*i], y = bx[2*i+1];
        bool ok = (by[i] == bp[i]);
        g_batch[i] = make_float4(CC2*x, CC2*y, ok ? -CC*(x*x + y*y) : -1e30f, 0.f);
        if (ok) atomicAdd(&g_cnt, 1);
    }
}

__global__ void k_hist(const float* __restrict__ trp, const float* __restrict__ tep) {
    __shared__ int sh[2 * NBINS];
    int t = threadIdx.x;
    if (t < 2 * NBINS) sh[t] = 0;
    __syncthreads();
    int i = blockIdx.x * blockDim.x + t;
    if (i < NTR + NTE) {
        float p; int off;
        if (i < NTR) { p = trp[i]; off = 0; }
        else         { p = tep[i - NTR]; off = NBINS; }
        #pragma unroll
        for (int bb = 0; bb < NBINS; bb++) {
            float lo = (float)bb * (1.0f / 15.0f);
            float hi = (float)(bb + 1) * (1.0f / 15.0f);
            if (p > lo && p <= hi) atomicAdd(&sh[off + bb], 1);
        }
    }
    __syncthreads();
    if (t < NBINS) { if (sh[t]) atomicAdd(&g_htr[t], sh[t]); }
    else if (t < 2 * NBINS) { if (sh[t]) atomicAdd(&g_hte[t - NBINS], sh[t]); }
}

__global__ void k_filter(const float* __restrict__ mc, const float* __restrict__ W,
                         const float* __restrict__ bvec) {
    int g = blockIdx.x * blockDim.x + threadIdx.x;
    if (g >= NPTS) return;
    int bin = g / NMC;
    float qx = mc[2*g], qy = mc[2*g+1];
    float l[NCLS];
    float lmax = -FLT_MAX;
    #pragma unroll
    for (int c = 0; c < NCLS; c++) {
        float v = fmaf(qx, __ldg(&W[c]), fmaf(qy, __ldg(&W[NCLS + c]), __ldg(&bvec[c])));
        l[c] = v;
        lmax = fmaxf(lmax, v);
    }
    float s = 0.f;
    #pragma unroll
    for (int c = 0; c < NCLS; c++) s += __expf(l[c] - lmax);
    float hs = 1.0f / s;  // max softmax prob
    float lo = (float)bin * (1.0f / 15.0f);
    float hi = (float)(bin + 1) * (1.0f / 15.0f);
    if (hs >= lo && hs <= hi) {
        int slot = atomicAdd(&g_M, 1);
        g_px[slot] = qx;
        g_py[slot] = qy;
        g_pe[slot] = -CC * (qx*qx + qy*qy);
        g_pbin[slot] = bin;
    }
}

__global__ void __launch_bounds__(TILE) k_kde() {
    __shared__ float4 sd[CHUNK];
    const int M = g_M;
    const int tiles = (M + TILE - 1) / TILE;
    const int nitems = tiles * NCHUNKS;
    for (int item = blockIdx.x; item < nitems; item += gridDim.x) {
        int tile = item / NCHUNKS;
        int ch   = item - tile * NCHUNKS;
        int arr = c_carr[ch], start = c_cstart[ch], len = c_clen[ch];
        const float4* src = (arr == 0) ? (g_train + start)
                          : (arr == 1) ? (g_test + start)
                                       : (g_batch + start);
        __syncthreads();   // protect sd from previous iteration's readers
        for (int i = threadIdx.x; i < len; i += TILE) sd[i] = src[i];
        __syncthreads();

        int p = tile * TILE + threadIdx.x;
        if (p < M) {
            float qx = g_px[p], qy = g_py[p], e = g_pe[p];
            float s0 = 0.f, s1 = 0.f;
            int j = 0;
            for (; j + 4 <= len; j += 4) {
                float4 a = sd[j], b = sd[j+1], c = sd[j+2], d = sd[j+3];
                float t0 = fmaf(a.x, qx, fmaf(a.y, qy, a.z)) + e;
                float t1 = fmaf(b.x, qx, fmaf(b.y, qy, b.z)) + e;
                float t2 = fmaf(c.x, qx, fmaf(c.y, qy, c.z)) + e;
                float t3 = fmaf(d.x, qx, fmaf(d.y, qy, d.z)) + e;
                s0 += ex2f(t0);
                s1 += ex2f(t1);
                s0 += ex2f(t2);
                s1 += ex2f(t3);
            }
            for (; j < len; j++) {
                float4 a = sd[j];
                float t0 = fmaf(a.x, qx, fmaf(a.y, qy, a.z)) + e;
                s0 += ex2f(t0);
            }
            float* dst = (arr == 0) ? g_sums0 : (arr == 1) ? g_sums1 : g_sums2;
            atomicAdd(&dst[p], s0 + s1);
        }
    }
}

__global__ void k_final_pts() {
    const int M = g_M;
    const float cntf = (float)g_cnt;
    const float p_y = cntf / (float)NB;
    for (int p = blockIdx.x * blockDim.x + threadIdx.x; p < M;
         p += gridDim.x * blockDim.x) {
        int bin = g_pbin[p];
        float ktr = g_sums0[p] * (float)(1.0 / (NTR * KDE_NORM_D));
        float kte = g_sums1[p] * (float)(1.0 / (NTE * KDE_NORM_D));
        float kw  = g_sums2[p] / (fmaxf(cntf, 1.0f) * (float)KDE_NORM_D);
        float p_hs = kw * p_y / (ktr + 1e-8f);
        p_hs = fminf(fmaxf(p_hs, 0.0f), 1.0f);
        float ter = (float)g_hte[bin] / (float)NTE;
        float trr = (float)g_htr[bin] / (float)NTR;
        float d_t = (ter > 0.f) ? kte / ter : 0.f;
        float d_s = (trr > 0.f) ? ktr / trr : 0.f;
        atomicAdd(&g_integral[bin], (double)(p_hs * (d_t - d_s)));
    }
}

__global__ void k_ec(float* __restrict__ out) {
    double ec = 0.0;
    for (int b = 0; b < NBINS; b++) {
        float ter = (float)g_hte[b] / (float)NTE;
        if (ter > 0.f) {
            double integral = g_integral[b] / (double)NMC * 100.0;  // VOLUME
            ec += (double)ter * fabs(integral);
        }
    }
    out[0] = (float)ec;
}

// ---------- launch ----------
extern "C" void kernel_launch(void* const* d_in, const int* in_sizes, int n_in,
                              void* d_out, int out_size) {
    const float *bx = nullptr, *trp = nullptr, *tep = nullptr;
    const float *trx = nullptr, *tex = nullptr, *W = nullptr, *bv = nullptr, *mc = nullptr;
    const int *by = nullptr, *bp = nullptr;
    for (int i = 0; i < n_in; i++) {
        switch (in_sizes[i]) {
            case 2048:   bx = (const float*)d_in[i]; break;
            case 1024:   if (!by) by = (const int*)d_in[i]; else bp = (const int*)d_in[i]; break;
            case 20000:  if (!trp) trp = (const float*)d_in[i]; else tex = (const float*)d_in[i]; break;
            case 10000:  tep = (const float*)d_in[i]; break;
            case 40000:  trx = (const float*)d_in[i]; break;
            case 20:     W = (const float*)d_in[i]; break;
            case 10:     bv = (const float*)d_in[i]; break;
            case 300000: mc = (const float*)d_in[i]; break;
            default: break;
        }
    }

    k_zero<<<(NPTS + 255) / 256, 256>>>();
    k_prep<<<(NTR + 255) / 256, 256>>>(trx, tex, bx, by, bp);
    k_hist<<<(NTR + NTE + 255) / 256, 256>>>(trp, tep);
    k_filter<<<(NPTS + 255) / 256, 256>>>(mc, W, bv);
    k_kde<<<KDE_GRID, TILE>>>();
    k_final_pts<<<592, 256>>>();
    k_ec<<<1, 1>>>((float*)d_out);
}

// round 3
// speedup vs baseline: 1.1685x; 1.1685x over previous
#include <cuda_runtime.h>
#include <math.h>
#include <float.h>

#define NTR   20000
#define NTE   10000
#define NB    1024
#define NBINS 15
#define NMC   10000
#define NPTS  150000
#define NCLS  10

#define NC1D   8
#define NCELLS 64
#define INVCW  0.8f          // 1 / 1.25 cell width over [-5,5]

#define QT     128           // query tile
#define CH     1024          // data chunk
#define TR_CH  20
#define TE_CH  10
#define NCH    31            // 20 train + 10 test + 1 batch
#define MAXTILES 1172        // ceil(NPTS / QT)
#define CUT2   5.4f          // d^2 beyond which exp2(-CC*d^2) < 2^-43

#define NSH   (4 * NCELLS + 2 * NBINS + 1)   // 287

// c = log2(e) / (2*BW^2)
#define CC   8.014972449383130f
#define CC2  16.029944898766260f
#define KDE_NORM_D 0.5654866776461628

// ---------------- static device scratch ----------------
__device__ float4 g_train[NTR];      // sorted (u, v, f, 0)
__device__ float4 g_test[NTE];
__device__ float4 g_batch[NB];
__device__ float4 g_tq[NPTS];        // unsorted survivors (x, y, 0, bin-bits)
__device__ float4 g_q[NPTS];         // sorted survivors  (x, y, e, bin-bits)
__device__ float  g_s0[NPTS], g_s1[NPTS], g_s2[NPTS];
__device__ int    g_M, g_cnt;
__device__ int    g_ccnt[4 * NCELLS];   // [q | tr | te | ba] cell counts
__device__ int    g_cur[4 * NCELLS];    // scatter cursors (offsets)
__device__ int    g_htr[NBINS], g_hte[NBINS];
__device__ double g_integral[NBINS];
__device__ float4 g_cbb[NCH];           // chunk bbox (minx,miny,maxx,maxy)
__device__ float4 g_tbb[MAXTILES];      // tile  bbox

__device__ __forceinline__ float ex2f(float x) {
    float y;
    asm("ex2.approx.ftz.f32 %0, %1;" : "=f"(y) : "f"(x));
    return y;
}
__device__ __forceinline__ int cellof(float x, float y) {
    int cx = (int)((x + 5.0f) * INVCW);
    int cy = (int)((y + 5.0f) * INVCW);
    cx = min(NC1D - 1, max(0, cx));
    cy = min(NC1D - 1, max(0, cy));
    return cy * NC1D + cx;
}

// ---------------- kernels ----------------
__global__ void k_init() {
    int t = threadIdx.x;
    if (t == 0) { g_M = 0; g_cnt = 0; }
    if (t < 4 * NCELLS) g_ccnt[t] = 0;
    if (t < NBINS) { g_htr[t] = 0; g_hte[t] = 0; g_integral[t] = 0.0; }
}

// count cells (data + queries), histograms, correctness count, survivor compaction
__global__ void k_phase1(const float* __restrict__ trx, const float* __restrict__ tex,
                         const float* __restrict__ bx, const int* __restrict__ by,
                         const int* __restrict__ bp, const float* __restrict__ trp,
                         const float* __restrict__ tep, const float* __restrict__ mc,
                         const float* __restrict__ W, const float* __restrict__ bvec) {
    __shared__ int sh[NSH];  // 287: [qcells|trcells|tecells|bacells|htr|hte|cnt]
    int t = threadIdx.x;
    for (int s = t; s < NSH; s += 256) sh[s] = 0;
    __syncthreads();

    int i = blockIdx.x * blockDim.x + t;

    if (i < NTR) {
        atomicAdd(&sh[NCELLS + cellof(trx[2 * i], trx[2 * i + 1])], 1);
        float p = trp[i];
        #pragma unroll
        for (int b = 0; b < NBINS; b++) {
            float lo = (float)b * (1.0f / 15.0f);
            float hi = (float)(b + 1) * (1.0f / 15.0f);
            if (p > lo && p <= hi) atomicAdd(&sh[4 * NCELLS + b], 1);
        }
    }
    if (i < NTE) {
        atomicAdd(&sh[2 * NCELLS + cellof(tex[2 * i], tex[2 * i + 1])], 1);
        float p = tep[i];
        #pragma unroll
        for (int b = 0; b < NBINS; b++) {
            float lo = (float)b * (1.0f / 15.0f);
            float hi = (float)(b + 1) * (1.0f / 15.0f);
            if (p > lo && p <= hi) atomicAdd(&sh[4 * NCELLS + NBINS + b], 1);
        }
    }
    if (i < NB) {
        atomicAdd(&sh[3 * NCELLS + cellof(bx[2 * i], bx[2 * i + 1])], 1);
        if (by[i] == bp[i]) atomicAdd(&sh[4 * NCELLS + 2 * NBINS], 1);
    }

    // filter MC points
    bool pass = false;
    float qx = 0.f, qy = 0.f;
    int bin = 0;
    if (i < NPTS) {
        bin = i / NMC;
        qx = mc[2 * i]; qy = mc[2 * i + 1];
        float l[NCLS], lmax = -FLT_MAX;
        #pragma unroll
        for (int c = 0; c < NCLS; c++) {
            float v = fmaf(qx, __ldg(&W[c]), fmaf(qy, __ldg(&W[NCLS + c]), __ldg(&bvec[c])));
            l[c] = v; lmax = fmaxf(lmax, v);
        }
        float s = 0.f;
        #pragma unroll
        for (int c = 0; c < NCLS; c++) s += __expf(l[c] - lmax);
        float hs = 1.0f / s;
        float lo = (float)bin * (1.0f / 15.0f);
        float hi = (float)(bin + 1) * (1.0f / 15.0f);
        pass = (hs >= lo && hs <= hi);
    }
    unsigned mask = __ballot_sync(0xffffffffu, pass);
    if (pass) {
        int lane = t & 31;
        int leader = __ffs(mask) - 1;
        int rank = __popc(mask & ((1u << lane) - 1));
        int base = 0;
        if (lane == leader) base = atomicAdd(&g_M, __popc(mask));
        base = __shfl_sync(mask, base, leader);
        g_tq[base + rank] = make_float4(qx, qy, 0.f, __int_as_float(bin));
        atomicAdd(&sh[cellof(qx, qy)], 1);
    }

    __syncthreads();
    for (int s = t; s < NSH; s += 256) {
        int v = sh[s];
        if (!v) continue;
        if (s < 4 * NCELLS)                    atomicAdd(&g_ccnt[s], v);
        else if (s < 4 * NCELLS + NBINS)       atomicAdd(&g_htr[s - 4 * NCELLS], v);
        else if (s < 4 * NCELLS + 2 * NBINS)   atomicAdd(&g_hte[s - 4 * NCELLS - NBINS], v);
        else                                   atomicAdd(&g_cnt, v);
    }
}

__global__ void k_scan() {
    int a = threadIdx.x;           // 4 arrays, one thread each
    if (a < 4) {
        int run = 0;
        for (int c = 0; c < NCELLS; c++) {
            g_cur[a * NCELLS + c] = run;
            run += g_ccnt[a * NCELLS + c];
        }
    }
}

__global__ void k_scatter(const float* __restrict__ trx, const float* __restrict__ tex,
                          const float* __restrict__ bx, const int* __restrict__ by,
                          const int* __restrict__ bp) {
    int i = blockIdx.x * blockDim.x + threadIdx.x;
    if (i < NTR) {
        float x = trx[2 * i], y = trx[2 * i + 1];
        int pos = atomicAdd(&g_cur[NCELLS + cellof(x, y)], 1);
        g_train[pos] = make_float4(CC2 * x, CC2 * y, -CC * (x * x + y * y), 0.f);
    }
    if (i < NTE) {
        float x = tex[2 * i], y = tex[2 * i + 1];
        int pos = atomicAdd(&g_cur[2 * NCELLS + cellof(x, y)], 1);
        g_test[pos] = make_float4(CC2 * x, CC2 * y, -CC * (x * x + y * y), 0.f);
    }
    if (i < NB) {
        float x = bx[2 * i], y = bx[2 * i + 1];
        bool ok = (by[i] == bp[i]);
        int pos = atomicAdd(&g_cur[3 * NCELLS + cellof(x, y)], 1);
        g_batch[pos] = make_float4(CC2 * x, CC2 * y, ok ? -CC * (x * x + y * y) : -1e30f, 0.f);
    }
    if (i < g_M) {
        float4 q = g_tq[i];
        int pos = atomicAdd(&g_cur[cellof(q.x, q.y)], 1);
        g_q[pos] = make_float4(q.x, q.y, -CC * (q.x * q.x + q.y * q.y), q.w);
        g_s0[pos] = 0.f; g_s1[pos] = 0.f; g_s2[pos] = 0.f;
    }
}

// per-chunk and per-tile bboxes
__global__ void __launch_bounds__(128) k_bbox() {
    __shared__ float4 red[128];
    int b = blockIdx.x, t = threadIdx.x;
    float mnx = FLT_MAX, mny = FLT_MAX, mxx = -FLT_MAX, mxy = -FLT_MAX;
    if (b < NCH) {
        const float4* src; int start, len;
        if (b < TR_CH)      { src = g_train; start = b * CH;            len = min(CH, NTR - start); }
        else if (b < TR_CH + TE_CH) { src = g_test; start = (b - TR_CH) * CH; len = min(CH, NTE - start); }
        else                { src = g_batch; start = 0;                 len = NB; }
        for (int j = t; j < len; j += 128) {
            float4 d = src[start + j];
            float x = d.x * (1.0f / CC2), y = d.y * (1.0f / CC2);
            mnx = fminf(mnx, x); mny = fminf(mny, y);
            mxx = fmaxf(mxx, x); mxy = fmaxf(mxy, y);
        }
    } else {
        int tile = b - NCH;
        int start = tile * QT;
        int M = g_M;
        if (start >= M) return;
        int len = min(QT, M - start);
        if (t < len) {
            float4 q = g_q[start + t];
            mnx = mxx = q.x; mny = mxy = q.y;
        }
    }
    red[t] = make_float4(mnx, mny, mxx, mxy);
    __syncthreads();
    for (int s = 64; s > 0; s >>= 1) {
        if (t < s) {
            float4 o = red[t + s];
            red[t].x = fminf(red[t].x, o.x);
            red[t].y = fminf(red[t].y, o.y);
            red[t].z = fmaxf(red[t].z, o.z);
            red[t].w = fmaxf(red[t].w, o.w);
        }
        __syncthreads();
    }
    if (t == 0) {
        if (b < NCH) g_cbb[b] = red[0];
        else         g_tbb[b - NCH] = red[0];
    }
}

__global__ void __launch_bounds__(QT) k_kde() {
    __shared__ float4 sd[CH];
    const int M = g_M;
    const int tiles = (M + QT - 1) / QT;
    const int nitems = tiles * NCH;
    const int p_in_tile = threadIdx.x;

    for (int item = blockIdx.x; item < nitems; item += gridDim.x) {
        int tile = item / NCH;
        int ch   = item - tile * NCH;

        float4 cb = g_cbb[ch];
        float4 tb = g_tbb[tile];
        float dx = fmaxf(0.f, fmaxf(cb.x - tb.z, tb.x - cb.z));
        float dy = fmaxf(0.f, fmaxf(cb.y - tb.w, tb.y - cb.w));
        if (dx * dx + dy * dy > CUT2) continue;   // uniform across block

        const float4* src; int start, len;
        float* dst;
        if (ch < TR_CH)             { src = g_train; start = ch * CH;            len = min(CH, NTR - start); dst = g_s0; }
        else if (ch < TR_CH + TE_CH){ src = g_test;  start = (ch - TR_CH) * CH;  len = min(CH, NTE - start); dst = g_s1; }
        else                        { src = g_batch; start = 0;                  len = NB;                   dst = g_s2; }

        __syncthreads();   // protect sd from previous item's readers
        for (int i = threadIdx.x; i < len; i += QT) sd[i] = src[start + i];
        __syncthreads();

        int p = tile * QT + p_in_tile;
        float qx = 0.f, qy = 0.f, e = 0.f;
        bool active = false;
        if (p < M) {
            float4 q = g_q[p];
            qx = q.x; qy = q.y; e = q.z;
            float qdx = fmaxf(0.f, fmaxf(cb.x - qx, qx - cb.z));
            float qdy = fmaxf(0.f, fmaxf(cb.y - qy, qy - cb.w));
            active = (qdx * qdx + qdy * qdy) <= CUT2;
        }
        if (__ballot_sync(0xffffffffu, active) == 0u) continue;  // whole warp far
        if (active) {
            float s0 = 0.f, s1 = 0.f;
            int j = 0;
            for (; j + 4 <= len; j += 4) {
                float4 a = sd[j], b4 = sd[j + 1], c4 = sd[j + 2], d4 = sd[j + 3];
                float t0 = fmaf(a.x,  qx, fmaf(a.y,  qy, a.z))  + e;
                float t1 = fmaf(b4.x, qx, fmaf(b4.y, qy, b4.z)) + e;
                float t2 = fmaf(c4.x, qx, fmaf(c4.y, qy, c4.z)) + e;
                float t3 = fmaf(d4.x, qx, fmaf(d4.y, qy, d4.z)) + e;
                s0 += ex2f(t0); s1 += ex2f(t1);
                s0 += ex2f(t2); s1 += ex2f(t3);
            }
            for (; j < len; j++) {
                float4 a = sd[j];
                s0 += ex2f(fmaf(a.x, qx, fmaf(a.y, qy, a.z)) + e);
            }
            atomicAdd(&dst[p], s0 + s1);
        }
    }
}

__global__ void k_final_pts() {
    const int M = g_M;
    const float cntf = (float)g_cnt;
    const float p_y = cntf / (float)NB;
    for (int p = blockIdx.x * blockDim.x + threadIdx.x; p < M;
         p += gridDim.x * blockDim.x) {
        int bin = __float_as_int(g_q[p].w);
        float ktr = g_s0[p] * (float)(1.0 / (NTR * KDE_NORM_D));
        float kte = g_s1[p] * (float)(1.0 / (NTE * KDE_NORM_D));
        float kw  = g_s2[p] / (fmaxf(cntf, 1.0f) * (float)KDE_NORM_D);
        float p_hs = kw * p_y / (ktr + 1e-8f);
        p_hs = fminf(fmaxf(p_hs, 0.0f), 1.0f);
        float ter = (float)g_hte[bin] / (float)NTE;
        float trr = (float)g_htr[bin] / (float)NTR;
        float d_t = (ter > 0.f) ? kte / ter : 0.f;
        float d_s = (trr > 0.f) ? ktr / trr : 0.f;
        atomicAdd(&g_integral[bin], (double)(p_hs * (d_t - d_s)));
    }
}

__global__ void k_ec(float* __restrict__ out) {
    double ec = 0.0;
    for (int b = 0; b < NBINS; b++) {
        float ter = (float)g_hte[b] / (float)NTE;
        if (ter > 0.f) {
            double integral = g_integral[b] / (double)NMC * 100.0;  // VOLUME
            ec += (double)ter * fabs(integral);
        }
    }
    out[0] = (float)ec;
}

// ---------------- launch ----------------
extern "C" void kernel_launch(void* const* d_in, const int* in_sizes, int n_in,
                              void* d_out, int out_size) {
    const float *bx = nullptr, *trp = nullptr, *tep = nullptr;
    const float *trx = nullptr, *tex = nullptr, *W = nullptr, *bv = nullptr, *mc = nullptr;
    const int *by = nullptr, *bp = nullptr;
    for (int i = 0; i < n_in; i++) {
        switch (in_sizes[i]) {
            case 2048:   bx = (const float*)d_in[i]; break;
            case 1024:   if (!by) by = (const int*)d_in[i]; else bp = (const int*)d_in[i]; break;
            case 20000:  if (!trp) trp = (const float*)d_in[i]; else tex = (const float*)d_in[i]; break;
            case 10000:  tep = (const float*)d_in[i]; break;
            case 40000:  trx = (const float*)d_in[i]; break;
            case 20:     W = (const float*)d_in[i]; break;
            case 10:     bv = (const float*)d_in[i]; break;
            case 300000: mc = (const float*)d_in[i]; break;
            default: break;
        }
    }

    k_init<<<1, 256>>>();
    k_phase1<<<(NPTS + 255) / 256, 256>>>(trx, tex, bx, by, bp, trp, tep, mc, W, bv);
    k_scan<<<1, 32>>>();
    k_scatter<<<(NPTS + 255) / 256, 256>>>(trx, tex, bx, by, bp);
    k_bbox<<<NCH + MAXTILES, 128>>>();
    k_kde<<<2048, QT>>>();
    k_final_pts<<<(NPTS + 255) / 256, 256>>>();
    k_ec<<<1, 1>>>((float*)d_out);
}

// round 4
// speedup vs baseline: 1.2847x; 1.0994x over previous
#include <cuda_runtime.h>
#include <math.h>
#include <float.h>

#define NTR   20000
#define NTE   10000
#define NB    1024
#define NBINS 15
#define NMC   10000
#define NPTS  150000
#define NCLS  10

#define NC1D   8
#define NCELLS 64
#define INVCW  0.8f            // 1/1.25 cell width over [-5,5]

#define GRID  296
#define BLK   256
#define NWARP (BLK / 32)
#define SPAN  (GRID * BLK)

#define QT    256              // queries per tile (= BLK)
#define DCH   256              // data points per chunk
#define TRC   79               // ceil(20000/256)
#define TEC   40               // ceil(10000/256)
#define BAC   4
#define NCHK  (TRC + TEC + BAC)   // 123
#define MAXTILES ((NPTS + QT - 1) / QT)  // 586
#define CUT2  5.4f             // d^2 cutoff: exp2(-CC*5.4) < 2^-43

#define NSH   (4 * NCELLS + 2 * NBINS + 1)   // 287

// c = log2(e) / (2*BW^2)
#define CC   8.014972449383130f
#define CC2  16.029944898766260f
#define KDE_NORM_D 0.5654866776461628

// ---------------- static device scratch ----------------
__device__ float4 g_train[NTR];
__device__ float4 g_test[NTE];
__device__ float4 g_batch[NB];
__device__ float4 g_tq[NPTS];        // unsorted survivors (x, y, 0, bin-bits)
__device__ float4 g_q[NPTS];         // sorted survivors  (x, y, e, bin-bits)
__device__ float  g_s0[NPTS], g_s1[NPTS], g_s2[NPTS];
__device__ int    g_M, g_cnt;
__device__ int    g_ccnt[4 * NCELLS];   // [q | tr | te | ba] cell counts
__device__ int    g_cur[4 * NCELLS];    // exclusive offsets / cursors
__device__ int    g_htr[NBINS], g_hte[NBINS];
__device__ double g_integral[NBINS];
__device__ float4 g_cbb[NCHK];
__device__ float4 g_tbb[MAXTILES];
__device__ int    g_ticket;
__device__ __align__(128) int g_bar_cnt;
__device__ __align__(128) int g_bar_gen;

union ShU {
    int sh[NSH];                                  // phase A
    struct { int h[256]; int hbase[256]; } sc;    // phase C
    struct { float4 sd[DCH]; int item; } kd;      // phase E
    double bins[NBINS];                           // phase F
};

__device__ __forceinline__ float ex2f(float x) {
    float y;
    asm("ex2.approx.ftz.f32 %0, %1;" : "=f"(y) : "f"(x));
    return y;
}
__device__ __forceinline__ int cellof(float x, float y) {
    int cx = (int)((x + 5.0f) * INVCW);
    int cy = (int)((y + 5.0f) * INVCW);
    cx = min(NC1D - 1, max(0, cx));
    cy = min(NC1D - 1, max(0, cy));
    return cy * NC1D + cx;
}
__device__ __forceinline__ void chunk_info(int c, int& arr, int& start, int& len) {
    if (c < TRC)            { arr = 0; start = c * DCH;          len = min(DCH, NTR - start); }
    else if (c < TRC + TEC) { arr = 1; start = (c - TRC) * DCH;  len = min(DCH, NTE - start); }
    else                    { arr = 2; start = (c - TRC - TEC) * DCH; len = min(DCH, NB - start); }
}

// fence-cumulative grid barrier (all GRID blocks resident by construction)
__device__ __forceinline__ void gridbar() {
    __syncthreads();
    if (threadIdx.x == 0) {
        __threadfence();                       // release (cumulative over block via bar)
        int gen = atomicAdd(&g_bar_gen, 0);
        if (atomicAdd(&g_bar_cnt, 1) == GRID - 1) {
            atomicExch(&g_bar_cnt, 0);
            __threadfence();
            atomicExch(&g_bar_gen, gen + 1);
        } else {
            while (*(volatile int*)&g_bar_gen == gen) { __nanosleep(64); }
        }
        __threadfence();                       // acquire: flush L1D
    }
    __syncthreads();
}

__global__ void __launch_bounds__(BLK, 2) k_all(
    const float* __restrict__ trx, const float* __restrict__ tex,
    const float* __restrict__ bx, const int* __restrict__ by,
    const int* __restrict__ bp, const float* __restrict__ trp,
    const float* __restrict__ tep, const float* __restrict__ mc,
    const float* __restrict__ W, const float* __restrict__ bvec,
    float* __restrict__ out)
{
    __shared__ ShU u;
    const int tid = threadIdx.x;
    const int gid = blockIdx.x * BLK + tid;

    // ---------- phase 0: zero globals ----------
    if (gid < 4 * NCELLS) g_ccnt[gid] = 0;
    else if (gid < 4 * NCELLS + NBINS)       g_htr[gid - 4 * NCELLS] = 0;
    else if (gid < 4 * NCELLS + 2 * NBINS)   g_hte[gid - 4 * NCELLS - NBINS] = 0;
    else if (gid < 4 * NCELLS + 3 * NBINS)   g_integral[gid - 4 * NCELLS - 2 * NBINS] = 0.0;
    else if (gid == 4 * NCELLS + 3 * NBINS)  { g_M = 0; g_cnt = 0; g_ticket = 0; }
    gridbar();

    // ---------- phase A: cells + hists + cnt + filter/compact ----------
    for (int s = tid; s < NSH; s += BLK) u.sh[s] = 0;
    __syncthreads();
    for (int i0 = 0; i0 < NPTS; i0 += SPAN) {
        int i = i0 + gid;
        if (i < NTR) {
            atomicAdd(&u.sh[NCELLS + cellof(trx[2 * i], trx[2 * i + 1])], 1);
            float p = trp[i];
            #pragma unroll
            for (int b = 0; b < NBINS; b++) {
                float lo = (float)b * (1.0f / 15.0f);
                float hi = (float)(b + 1) * (1.0f / 15.0f);
                if (p > lo && p <= hi) atomicAdd(&u.sh[4 * NCELLS + b], 1);
            }
        }
        if (i < NTE) {
            atomicAdd(&u.sh[2 * NCELLS + cellof(tex[2 * i], tex[2 * i + 1])], 1);
            float p = tep[i];
            #pragma unroll
            for (int b = 0; b < NBINS; b++) {
                float lo = (float)b * (1.0f / 15.0f);
                float hi = (float)(b + 1) * (1.0f / 15.0f);
                if (p > lo && p <= hi) atomicAdd(&u.sh[4 * NCELLS + NBINS + b], 1);
            }
        }
        if (i < NB) {
            atomicAdd(&u.sh[3 * NCELLS + cellof(bx[2 * i], bx[2 * i + 1])], 1);
            if (by[i] == bp[i]) atomicAdd(&u.sh[4 * NCELLS + 2 * NBINS], 1);
        }
        bool pass = false;
        float qx = 0.f, qy = 0.f;
        int bin = 0;
        if (i < NPTS) {
            bin = i / NMC;
            qx = mc[2 * i]; qy = mc[2 * i + 1];
            float l[NCLS], lmax = -FLT_MAX;
            #pragma unroll
            for (int c = 0; c < NCLS; c++) {
                float v = fmaf(qx, __ldg(&W[c]), fmaf(qy, __ldg(&W[NCLS + c]), __ldg(&bvec[c])));
                l[c] = v; lmax = fmaxf(lmax, v);
            }
            float s = 0.f;
            #pragma unroll
            for (int c = 0; c < NCLS; c++) s += __expf(l[c] - lmax);
            float hs = 1.0f / s;
            float lo = (float)bin * (1.0f / 15.0f);
            float hi = (float)(bin + 1) * (1.0f / 15.0f);
            pass = (hs >= lo && hs <= hi);
        }
        unsigned mask = __ballot_sync(0xffffffffu, pass);
        if (pass) {
            int lane = tid & 31;
            int leader = __ffs(mask) - 1;
            int rank = __popc(mask & ((1u << lane) - 1));
            int base = 0;
            if (lane == leader) base = atomicAdd(&g_M, __popc(mask));
            base = __shfl_sync(mask, base, leader);
            g_tq[base + rank] = make_float4(qx, qy, 0.f, __int_as_float(bin));
            atomicAdd(&u.sh[cellof(qx, qy)], 1);
        }
    }
    __syncthreads();
    for (int s = tid; s < NSH; s += BLK) {
        int v = u.sh[s];
        if (!v) continue;
        if (s < 4 * NCELLS)                    atomicAdd(&g_ccnt[s], v);
        else if (s < 4 * NCELLS + NBINS)       atomicAdd(&g_htr[s - 4 * NCELLS], v);
        else if (s < 4 * NCELLS + 2 * NBINS)   atomicAdd(&g_hte[s - 4 * NCELLS - NBINS], v);
        else                                   atomicAdd(&g_cnt, v);
    }
    gridbar();

    // ---------- phase B: exclusive scans (block 0, 4 warps) ----------
    if (blockIdx.x == 0 && tid < 128) {
        int a = tid >> 5, lane = tid & 31;
        int base = a * NCELLS;
        int v0 = g_ccnt[base + lane], v1 = g_ccnt[base + 32 + lane];
        int s0 = v0;
        #pragma unroll
        for (int o = 1; o < 32; o <<= 1) {
            int n = __shfl_up_sync(0xffffffffu, s0, o);
            if (lane >= o) s0 += n;
        }
        int tot0 = __shfl_sync(0xffffffffu, s0, 31);
        int s1 = v1;
        #pragma unroll
        for (int o = 1; o < 32; o <<= 1) {
            int n = __shfl_up_sync(0xffffffffu, s1, o);
            if (lane >= o) s1 += n;
        }
        g_cur[base + lane]      = s0 - v0;
        g_cur[base + 32 + lane] = tot0 + s1 - v1;
    }
    gridbar();

    const int M = g_M;

    // ---------- phase C: block-aggregated scatter (single wave) ----------
    {
        for (int s = tid; s < 256; s += BLK) u.sc.h[s] = 0;
        __syncthreads();
        int i = gid;
        float qx = 0.f, qy = 0.f, qw = 0.f; int qc = -1, qr = 0;
        if (i < M) {
            float4 q = g_tq[i];
            qx = q.x; qy = q.y; qw = q.w;
            qc = cellof(qx, qy);
            qr = atomicAdd(&u.sc.h[qc], 1);
        }
        float tx = 0.f, ty = 0.f; int tc = -1, trk = 0;
        if (i < NTR) {
            tx = trx[2 * i]; ty = trx[2 * i + 1];
            tc = cellof(tx, ty);
            trk = atomicAdd(&u.sc.h[NCELLS + tc], 1);
        }
        float ex = 0.f, ey = 0.f; int ecl = -1, erk = 0;
        if (i < NTE) {
            ex = tex[2 * i]; ey = tex[2 * i + 1];
            ecl = cellof(ex, ey);
            erk = atomicAdd(&u.sc.h[2 * NCELLS + ecl], 1);
        }
        float bx_ = 0.f, by_ = 0.f; int bcl = -1, brk = 0; bool bok = false;
        if (i < NB) {
            bx_ = bx[2 * i]; by_ = bx[2 * i + 1];
            bok = (by[i] == bp[i]);
            bcl = cellof(bx_, by_);
            brk = atomicAdd(&u.sc.h[3 * NCELLS + bcl], 1);
        }
        __syncthreads();
        for (int s = tid; s < 256; s += BLK) {
            int c = u.sc.h[s];
            if (c) u.sc.hbase[s] = atomicAdd(&g_cur[s], c);
        }
        __syncthreads();
        if (qc >= 0) {
            int pos = u.sc.hbase[qc] + qr;
            g_q[pos] = make_float4(qx, qy, -CC * (qx * qx + qy * qy), qw);
            g_s0[pos] = 0.f; g_s1[pos] = 0.f; g_s2[pos] = 0.f;
        }
        if (tc >= 0) {
            int pos = u.sc.hbase[NCELLS + tc] + trk;
            g_train[pos] = make_float4(CC2 * tx, CC2 * ty, -CC * (tx * tx + ty * ty), 0.f);
        }
        if (ecl >= 0) {
            int pos = u.sc.hbase[2 * NCELLS + ecl] + erk;
            g_test[pos] = make_float4(CC2 * ex, CC2 * ey, -CC * (ex * ex + ey * ey), 0.f);
        }
        if (bcl >= 0) {
            int pos = u.sc.hbase[3 * NCELLS + bcl] + brk;
            g_batch[pos] = make_float4(CC2 * bx_, CC2 * by_,
                                       bok ? -CC * (bx_ * bx_ + by_ * by_) : -1e30f, 0.f);
        }
    }
    gridbar();

    // ---------- phase D: bboxes (warp per item) ----------
    const int tiles = (M + QT - 1) / QT;
    {
        int gw = blockIdx.x * NWARP + (tid >> 5);
        int lane = tid & 31;
        for (int it = gw; it < NCHK + tiles; it += GRID * NWARP) {
            float mnx = FLT_MAX, mny = FLT_MAX, mxx = -FLT_MAX, mxy = -FLT_MAX;
            if (it < NCHK) {
                int arr, start, len;
                chunk_info(it, arr, start, len);
                const float4* src = arr == 0 ? g_train : arr == 1 ? g_test : g_batch;
                for (int j = lane; j < len; j += 32) {
                    float4 d = src[start + j];
                    float x = d.x * (1.0f / CC2), y = d.y * (1.0f / CC2);
                    mnx = fminf(mnx, x); mxx = fmaxf(mxx, x);
                    mny = fminf(mny, y); mxy = fmaxf(mxy, y);
                }
            } else {
                int tile = it - NCHK;
                int start = tile * QT;
                int len = min(QT, M - start);
                for (int j = lane; j < len; j += 32) {
                    float4 q = g_q[start + j];
                    mnx = fminf(mnx, q.x); mxx = fmaxf(mxx, q.x);
                    mny = fminf(mny, q.y); mxy = fmaxf(mxy, q.y);
                }
            }
            #pragma unroll
            for (int o = 16; o; o >>= 1) {
                mnx = fminf(mnx, __shfl_xor_sync(0xffffffffu, mnx, o));
                mny = fminf(mny, __shfl_xor_sync(0xffffffffu, mny, o));
                mxx = fmaxf(mxx, __shfl_xor_sync(0xffffffffu, mxx, o));
                mxy = fmaxf(mxy, __shfl_xor_sync(0xffffffffu, mxy, o));
            }
            if (lane == 0) {
                float4 bb = make_float4(mnx, mny, mxx, mxy);
                if (it < NCHK) g_cbb[it] = bb;
                else           g_tbb[it - NCHK] = bb;
            }
        }
    }
    gridbar();

    // ---------- phase E: KDE over dynamic (tile, chunk) items ----------
    {
        const int nitems = tiles * NCHK;
        for (;;) {
            if (tid == 0) u.kd.item = atomicAdd(&g_ticket, 1);
            __syncthreads();
            int item = u.kd.item;
            __syncthreads();
            if (item >= nitems) break;
            int tile = item / NCHK;
            int c = item - tile * NCHK;
            float4 cb = g_cbb[c];
            float4 tb = g_tbb[tile];
            float ddx = fmaxf(0.f, fmaxf(cb.x - tb.z, tb.x - cb.z));
            float ddy = fmaxf(0.f, fmaxf(cb.y - tb.w, tb.y - cb.w));
            if (ddx * ddx + ddy * ddy > CUT2) continue;   // uniform skip

            int arr, start, len;
            chunk_info(c, arr, start, len);
            const float4* src = arr == 0 ? g_train : arr == 1 ? g_test : g_batch;
            if (tid < len) u.kd.sd[tid] = src[start + tid];
            __syncthreads();

            int p = tile * QT + tid;
            bool active = false;
            float qx = 0.f, qy = 0.f, e = 0.f;
            if (p < M) {
                float4 q = g_q[p];
                qx = q.x; qy = q.y; e = q.z;
                float a = fmaxf(0.f, fmaxf(cb.x - qx, qx - cb.z));
                float b2 = fmaxf(0.f, fmaxf(cb.y - qy, qy - cb.w));
                active = (a * a + b2 * b2) <= CUT2;
            }
            if (__ballot_sync(0xffffffffu, active) == 0u) continue;   // warp skip
            if (active) {
                float s0 = 0.f, s1 = 0.f;
                int j = 0;
                for (; j + 4 <= len; j += 4) {
                    float4 a4 = u.kd.sd[j], b4 = u.kd.sd[j + 1];
                    float4 c4 = u.kd.sd[j + 2], d4 = u.kd.sd[j + 3];
                    float t0 = fmaf(a4.x, qx, fmaf(a4.y, qy, a4.z)) + e;
                    float t1 = fmaf(b4.x, qx, fmaf(b4.y, qy, b4.z)) + e;
                    float t2 = fmaf(c4.x, qx, fmaf(c4.y, qy, c4.z)) + e;
                    float t3 = fmaf(d4.x, qx, fmaf(d4.y, qy, d4.z)) + e;
                    s0 += ex2f(t0); s1 += ex2f(t1);
                    s0 += ex2f(t2); s1 += ex2f(t3);
                }
                for (; j < len; j++) {
                    float4 a4 = u.kd.sd[j];
                    s0 += ex2f(fmaf(a4.x, qx, fmaf(a4.y, qy, a4.z)) + e);
                }
                float* dst = arr == 0 ? g_s0 : arr == 1 ? g_s1 : g_s2;
                atomicAdd(&dst[p], s0 + s1);
            }
        }
    }
    gridbar();

    // ---------- phase F: per-point finalize + per-bin integral ----------
    {
        for (int s = tid; s < NBINS; s += BLK) u.bins[s] = 0.0;
        __syncthreads();
        float cntf = (float)g_cnt;
        float p_y = cntf / (float)NB;
        for (int p = gid; p < M; p += SPAN) {
            int bin = __float_as_int(g_q[p].w);
            float ktr = g_s0[p] * (float)(1.0 / (NTR * KDE_NORM_D));
            float kte = g_s1[p] * (float)(1.0 / (NTE * KDE_NORM_D));
            float kw  = g_s2[p] / (fmaxf(cntf, 1.0f) * (float)KDE_NORM_D);
            float p_hs = fminf(fmaxf(kw * p_y / (ktr + 1e-8f), 0.0f), 1.0f);
            float ter = (float)g_hte[bin] * (1.0f / NTE);
            float trr = (float)g_htr[bin] * (1.0f / NTR);
            float d_t = (ter > 0.f) ? kte / ter : 0.f;
            float d_s = (trr > 0.f) ? ktr / trr : 0.f;
            atomicAdd(&u.bins[bin], (double)(p_hs * (d_t - d_s)));
        }
        __syncthreads();
        for (int s = tid; s < NBINS; s += BLK) {
            double v = u.bins[s];
            if (v != 0.0) atomicAdd(&g_integral[s], v);
        }
    }
    gridbar();

    // ---------- phase G: final scalar ----------
    if (blockIdx.x == 0 && tid == 0) {
        double ec = 0.0;
        for (int b = 0; b < NBINS; b++) {
            float ter = (float)g_hte[b] * (1.0f / NTE);
            if (ter > 0.f) {
                double integ = g_integral[b] / (double)NMC * 100.0;   // VOLUME
                ec += (double)ter * fabs(integ);
            }
        }
        out[0] = (float)ec;
    }
}

// ---------------- launch ----------------
extern "C" void kernel_launch(void* const* d_in, const int* in_sizes, int n_in,
                              void* d_out, int out_size) {
    const float *bx = nullptr, *trp = nullptr, *tep = nullptr;
    const float *trx = nullptr, *tex = nullptr, *W = nullptr, *bv = nullptr, *mc = nullptr;
    const int *by = nullptr, *bp = nullptr;
    for (int i = 0; i < n_in; i++) {
        switch (in_sizes[i]) {
            case 2048:   bx = (const float*)d_in[i]; break;
            case 1024:   if (!by) by = (const int*)d_in[i]; else bp = (const int*)d_in[i]; break;
            case 20000:  if (!trp) trp = (const float*)d_in[i]; else tex = (const float*)d_in[i]; break;
            case 10000:  tep = (const float*)d_in[i]; break;
            case 40000:  trx = (const float*)d_in[i]; break;
            case 20:     W = (const float*)d_in[i]; break;
            case 10:     bv = (const float*)d_in[i]; break;
            case 300000: mc = (const float*)d_in[i]; break;
            default: break;
        }
    }
    k_all<<<GRID, BLK>>>(trx, tex, bx, by, bp, trp, tep, mc, W, bv, (float*)d_out);
}